// round 11
// baseline (speedup 1.0000x reference)
#include <cuda_runtime.h>
#include <cuda_fp16.h>
#include <cstdint>
#include <cstring>

#define NN 100000
#define EE 1600000
#define NC 10000
#define GG 1000
#define ND 32
#define ED 8
#define NL 4
#define NB ((NN + 255) / 256)   // 391 scan blocks

// ---------------- scratch (device globals; no allocation allowed) -----------
__device__ float g_h[NN * ND];      // node embeddings (fp32)
__device__ uint4 g_eh[EE];          // edge embeddings fp16x8, DST-SORTED order
__device__ uint4 g_Ph[NN];          // h @ We[l][0:32]  fp16x8
__device__ uint4 g_Qh[NN];          // h @ We[l][32:64] fp16x8
__device__ float g_agg[NN * ED];    // segment-sum accumulator (zero-invariant)
// counting-sort scratch
__device__ unsigned g_cnt[NN];
__device__ unsigned g_off[NN];
__device__ unsigned g_cur[NN];
__device__ unsigned g_bsum[NB];
__device__ unsigned g_bsumoff[NB];
__device__ int g_ssrc[EE];          // sorted src
__device__ int g_sdst[EE];          // sorted dst
// final stage
__device__ float g_logits[NC];
__device__ unsigned g_mx[GG];
__device__ float g_sum[GG];

// ---------------- helpers ----------------------------------------------------
__device__ __forceinline__ unsigned enc_f(float f) {
    unsigned u = __float_as_uint(f);
    return (u & 0x80000000u) ? ~u : (u | 0x80000000u);
}
__device__ __forceinline__ float dec_f(unsigned u) {
    return (u & 0x80000000u) ? __uint_as_float(u & 0x7FFFFFFFu)
                             : __uint_as_float(~u);
}
__device__ __forceinline__ void red_add_v4(float* p, float a, float b, float c, float d) {
    asm volatile("red.global.add.v4.f32 [%0], {%1,%2,%3,%4};"
                 :: "l"(p), "f"(a), "f"(b), "f"(c), "f"(d) : "memory");
}
__device__ __forceinline__ unsigned h2u(__half2 h) {
    unsigned u; memcpy(&u, &h, 4); return u;
}
__device__ __forceinline__ float2 u2f2(unsigned u) {
    __half2 h; memcpy(&h, &u, 4); return __half22float2(h);
}
__device__ __forceinline__ uint4 pack8h(const float* v) {
    uint4 r;
    r.x = h2u(__floats2half2_rn(v[0], v[1]));
    r.y = h2u(__floats2half2_rn(v[2], v[3]));
    r.z = h2u(__floats2half2_rn(v[4], v[5]));
    r.w = h2u(__floats2half2_rn(v[6], v[7]));
    return r;
}
__device__ __forceinline__ void unpack8h(uint4 u, float* v) {
    float2 a = u2f2(u.x), b = u2f2(u.y), c = u2f2(u.z), d = u2f2(u.w);
    v[0]=a.x; v[1]=a.y; v[2]=b.x; v[3]=b.y; v[4]=c.x; v[5]=c.y; v[6]=d.x; v[7]=d.y;
}

// ================= counting sort by dst =======================================
__global__ void k_zero(unsigned n_extra_gg) {
    int i = blockIdx.x * blockDim.x + threadIdx.x;
    if (i < NN) g_cnt[i] = 0u;
    if (i < GG) { g_mx[i] = 0u; g_sum[i] = 0.f; }
    (void)n_extra_gg;
}

__global__ void k_hist(const int* __restrict__ edge_index) {
    int i = blockIdx.x * blockDim.x + threadIdx.x;
    if (i < EE) atomicAdd(&g_cnt[edge_index[EE + i]], 1u);
}

__global__ void k_scan1() {
    __shared__ unsigned s[256];
    int t = threadIdx.x;
    int gid = blockIdx.x * 256 + t;
    unsigned v = (gid < NN) ? g_cnt[gid] : 0u;
    s[t] = v;
    __syncthreads();
#pragma unroll
    for (int off = 1; off < 256; off <<= 1) {
        unsigned x = (t >= off) ? s[t - off] : 0u;
        __syncthreads();
        s[t] += x;
        __syncthreads();
    }
    if (gid < NN) g_off[gid] = s[t] - v;      // exclusive within block
    if (t == 255) g_bsum[blockIdx.x] = s[255];
}

__global__ void k_scan2() {
    __shared__ unsigned s[512];
    int t = threadIdx.x;
    unsigned v = (t < NB) ? g_bsum[t] : 0u;
    s[t] = v;
    __syncthreads();
#pragma unroll
    for (int off = 1; off < 512; off <<= 1) {
        unsigned x = (t >= off) ? s[t - off] : 0u;
        __syncthreads();
        s[t] += x;
        __syncthreads();
    }
    if (t < NB) g_bsumoff[t] = s[t] - v;      // exclusive block offsets
}

__global__ void k_scan3() {
    int gid = blockIdx.x * 256 + threadIdx.x;
    if (gid < NN) {
        unsigned o = g_off[gid] + g_bsumoff[blockIdx.x];
        g_off[gid] = o;
        g_cur[gid] = o;
    }
}

// scatter edges into dst-sorted order AND init e = attr @ We_in + be_in (fp16)
__global__ void k_scatter(const int* __restrict__ edge_index,
                          const float* __restrict__ edge_attr,
                          const float* __restrict__ We_in,
                          const float* __restrict__ be_in) {
    __shared__ float sw[ED], sb[ED];
    if (threadIdx.x < ED) { sw[threadIdx.x] = We_in[threadIdx.x]; sb[threadIdx.x] = be_in[threadIdx.x]; }
    __syncthreads();
    int i = blockIdx.x * blockDim.x + threadIdx.x;
    if (i >= EE) return;
    int s = edge_index[i];
    int d = edge_index[EE + i];
    float a = edge_attr[i];
    unsigned pos = atomicAdd(&g_cur[d], 1u);
    g_ssrc[pos] = s;
    g_sdst[pos] = d;
    float v[ED];
#pragma unroll
    for (int j = 0; j < ED; j++) v[j] = a * sw[j] + sb[j];
    g_eh[pos] = pack8h(v);
}

// ---------------- init: h = x @ Wn_in + bn_in; P0/Q0 from We_l[0] ------------
__global__ void k_init_nodes(const float* __restrict__ x,
                             const float* __restrict__ Wn_in,
                             const float* __restrict__ bn_in,
                             const float* __restrict__ We_l) {  // layer 0 block
    __shared__ float sW[2 * ND], sB[ND], sWa[ND * ED], sWb[ND * ED];
    for (int t = threadIdx.x; t < 2 * ND; t += blockDim.x) sW[t] = Wn_in[t];
    for (int t = threadIdx.x; t < ND; t += blockDim.x) sB[t] = bn_in[t];
    for (int t = threadIdx.x; t < ND * ED; t += blockDim.x) {
        sWa[t] = We_l[t];               // rows 0..31
        sWb[t] = We_l[ND * ED + t];     // rows 32..63
    }
    __syncthreads();
    int i = blockIdx.x * blockDim.x + threadIdx.x;
    if (i >= NN) return;
    float x0 = x[2 * i], x1 = x[2 * i + 1];
    float h[ND];
#pragma unroll
    for (int j = 0; j < ND; j++) h[j] = x0 * sW[j] + x1 * sW[ND + j] + sB[j];
    float4* ho = (float4*)(g_h + (size_t)i * ND);
#pragma unroll
    for (int j4 = 0; j4 < ND / 4; j4++)
        ho[j4] = make_float4(h[4*j4], h[4*j4+1], h[4*j4+2], h[4*j4+3]);
    float p[ED], q[ED];
#pragma unroll
    for (int t = 0; t < ED; t++) { p[t] = 0.f; q[t] = 0.f; }
#pragma unroll
    for (int k = 0; k < ND; k++) {
        float hk = h[k];
#pragma unroll
        for (int t = 0; t < ED; t++) {
            p[t] += hk * sWa[k * ED + t];
            q[t] += hk * sWb[k * ED + t];
        }
    }
    g_Ph[i] = pack8h(p);
    g_Qh[i] = pack8h(q);
}

// ---------------- per-layer edge kernel (2 sorted edges / thread) ------------
// new_e = relu(P[src] + Q[dst] + e @ Wc + be);  agg[dst] += new_e;  e += new_e
__global__ void __launch_bounds__(256, 5)
k_edge(const float* __restrict__ We_l,   // full [L,72,8]
       const float* __restrict__ be_l,   // full [L,8]
       int layer) {
    __shared__ float sWc[ED * ED], sBe[ED];
    {
        const float* Wc = We_l + (size_t)layer * (2 * ND + ED) * ED + 2 * ND * ED;
        if (threadIdx.x < ED * ED) sWc[threadIdx.x] = Wc[threadIdx.x];
        if (threadIdx.x < ED) sBe[threadIdx.x] = be_l[layer * ED + threadIdx.x];
    }
    __syncthreads();
    int t2 = blockIdx.x * blockDim.x + threadIdx.x;
    int i0 = t2 * 2;
    if (i0 >= EE) return;
    int2 sp = ((const int2*)g_ssrc)[t2];
    int2 dp = ((const int2*)g_sdst)[t2];
    // random P gathers (1 line each); Q gathers mostly same line after sort
    uint4 pv0 = __ldg(&g_Ph[sp.x]);
    uint4 pv1 = __ldg(&g_Ph[sp.y]);
    uint4 qv0 = __ldg(&g_Qh[dp.x]);
    uint4 qv1 = __ldg(&g_Qh[dp.y]);
    uint4 ea0 = g_eh[i0];
    uint4 ea1 = g_eh[i0 + 1];

    float m0[ED], m1[ED];
    unpack8h(ea0, m0);
    unpack8h(ea1, m1);
    float t0[ED], t1[ED];
#pragma unroll
    for (int j = 0; j < ED; j++) { t0[j] = sBe[j]; t1[j] = sBe[j]; }
#pragma unroll
    for (int k = 0; k < ED; k++) {
        float a = m0[k], b = m1[k];
#pragma unroll
        for (int j = 0; j < ED; j++) {
            float w = sWc[k * ED + j];
            t0[j] += a * w;
            t1[j] += b * w;
        }
    }
    float ne0[ED], ne1[ED];
    {
        const unsigned* pu0 = &pv0.x; const unsigned* qu0 = &qv0.x;
        const unsigned* pu1 = &pv1.x; const unsigned* qu1 = &qv1.x;
#pragma unroll
        for (int jp = 0; jp < 4; jp++) {
            float2 pf0 = u2f2(pu0[jp]), qf0 = u2f2(qu0[jp]);
            float2 pf1 = u2f2(pu1[jp]), qf1 = u2f2(qu1[jp]);
            float v0a = t0[2*jp]   + pf0.x + qf0.x;
            float v0b = t0[2*jp+1] + pf0.y + qf0.y;
            float v1a = t1[2*jp]   + pf1.x + qf1.x;
            float v1b = t1[2*jp+1] + pf1.y + qf1.y;
            ne0[2*jp]   = v0a > 0.f ? v0a : 0.f;
            ne0[2*jp+1] = v0b > 0.f ? v0b : 0.f;
            ne1[2*jp]   = v1a > 0.f ? v1a : 0.f;
            ne1[2*jp+1] = v1b > 0.f ? v1b : 0.f;
        }
    }
    if (dp.x == dp.y) {
        // common after sort: merge the two contributions, single red pair
        float* a0 = g_agg + (size_t)dp.x * ED;
        red_add_v4(a0,     ne0[0]+ne1[0], ne0[1]+ne1[1], ne0[2]+ne1[2], ne0[3]+ne1[3]);
        red_add_v4(a0 + 4, ne0[4]+ne1[4], ne0[5]+ne1[5], ne0[6]+ne1[6], ne0[7]+ne1[7]);
    } else {
        float* a0 = g_agg + (size_t)dp.x * ED;
        float* a1 = g_agg + (size_t)dp.y * ED;
        red_add_v4(a0,     ne0[0], ne0[1], ne0[2], ne0[3]);
        red_add_v4(a0 + 4, ne0[4], ne0[5], ne0[6], ne0[7]);
        red_add_v4(a1,     ne1[0], ne1[1], ne1[2], ne1[3]);
        red_add_v4(a1 + 4, ne1[4], ne1[5], ne1[6], ne1[7]);
    }
    float r0[ED], r1[ED];
#pragma unroll
    for (int j = 0; j < ED; j++) { r0[j] = m0[j] + ne0[j]; r1[j] = m1[j] + ne1[j]; }
    g_eh[i0]     = pack8h(r0);
    g_eh[i0 + 1] = pack8h(r1);
}

// ---------------- per-layer node kernel --------------------------------------
__global__ void k_node(const float* __restrict__ Wn_l,  // full [L,40,32]
                       const float* __restrict__ bn_l,  // full [L,32]
                       const float* __restrict__ We_l,  // full [L,72,8]
                       int layer, int last) {
    __shared__ float sWn[(ND + ED) * ND], sBn[ND];
    __shared__ float sWa[ND * ED], sWb[ND * ED];
    {
        const float* Wn = Wn_l + (size_t)layer * (ND + ED) * ND;
        for (int tt = threadIdx.x; tt < (ND + ED) * ND; tt += blockDim.x) sWn[tt] = Wn[tt];
        for (int tt = threadIdx.x; tt < ND; tt += blockDim.x) sBn[tt] = bn_l[layer * ND + tt];
        if (!last) {
            const float* Wa = We_l + (size_t)(layer + 1) * (2 * ND + ED) * ED;
            for (int tt = threadIdx.x; tt < ND * ED; tt += blockDim.x) {
                sWa[tt] = Wa[tt];
                sWb[tt] = Wa[ND * ED + tt];
            }
        }
    }
    __syncthreads();
    int i = blockIdx.x * blockDim.x + threadIdx.x;
    if (i >= NN) return;
    float m[ND + ED];
    float4* hp = (float4*)(g_h + (size_t)i * ND);
#pragma unroll
    for (int j4 = 0; j4 < ND / 4; j4++) {
        float4 v = hp[j4];
        m[4*j4] = v.x; m[4*j4+1] = v.y; m[4*j4+2] = v.z; m[4*j4+3] = v.w;
    }
    float4* ag = (float4*)(g_agg + (size_t)i * ED);
    float4 a0 = ag[0], a1 = ag[1];
    m[ND+0]=a0.x; m[ND+1]=a0.y; m[ND+2]=a0.z; m[ND+3]=a0.w;
    m[ND+4]=a1.x; m[ND+5]=a1.y; m[ND+6]=a1.z; m[ND+7]=a1.w;
    ag[0] = make_float4(0.f, 0.f, 0.f, 0.f);
    ag[1] = make_float4(0.f, 0.f, 0.f, 0.f);

    float acc[ND];
#pragma unroll
    for (int j = 0; j < ND; j++) acc[j] = sBn[j];
    for (int k = 0; k < ND + ED; k++) {
        float mk = m[k];
#pragma unroll
        for (int j = 0; j < ND; j++) acc[j] += mk * sWn[k * ND + j];
    }
    float hn[ND];
#pragma unroll
    for (int j = 0; j < ND; j++) {
        float r = acc[j] > 0.f ? acc[j] : 0.f;
        hn[j] = m[j] + r;
    }
#pragma unroll
    for (int j4 = 0; j4 < ND / 4; j4++)
        hp[j4] = make_float4(hn[4*j4], hn[4*j4+1], hn[4*j4+2], hn[4*j4+3]);

    if (!last) {
        float p[ED], q[ED];
#pragma unroll
        for (int t = 0; t < ED; t++) { p[t] = 0.f; q[t] = 0.f; }
#pragma unroll
        for (int k = 0; k < ND; k++) {
            float hk = hn[k];
#pragma unroll
            for (int t = 0; t < ED; t++) {
                p[t] += hk * sWa[k * ED + t];
                q[t] += hk * sWb[k * ED + t];
            }
        }
        g_Ph[i] = pack8h(p);
        g_Qh[i] = pack8h(q);
    }
}

// ---------------- final stage -------------------------------------------------
__global__ void k_cand(const int* __restrict__ cand,
                       const int* __restrict__ batch,
                       const float* __restrict__ Wout,
                       const float* __restrict__ bout) {
    int c = blockIdx.x * blockDim.x + threadIdx.x;
    if (c >= NC) return;
    int node = cand[c];
    const float* hr = g_h + (size_t)node * ND;
    float v = bout[0];
#pragma unroll
    for (int j = 0; j < ND; j++) v += hr[j] * Wout[j];
    g_logits[c] = v;
    int gidx = batch[node];
    atomicMax(&g_mx[gidx], enc_f(v));
}

__global__ void k_shift(const int* __restrict__ cand,
                        const int* __restrict__ batch,
                        float* __restrict__ out) {
    int c = blockIdx.x * blockDim.x + threadIdx.x;
    if (c >= NC) return;
    int gidx = batch[cand[c]];
    float s = g_logits[c] - dec_f(g_mx[gidx]);
    out[c] = s;
    atomicAdd(&g_sum[gidx], expf(s));
}

__global__ void k_finish(const int* __restrict__ cand,
                         const int* __restrict__ batch,
                         float* __restrict__ out) {
    int c = blockIdx.x * blockDim.x + threadIdx.x;
    if (c >= NC) return;
    int gidx = batch[cand[c]];
    out[c] = out[c] - logf(g_sum[gidx]);
}

// ---------------- launch ------------------------------------------------------
extern "C" void kernel_launch(void* const* d_in, const int* in_sizes, int n_in,
                              void* d_out, int out_size) {
    const float* x        = (const float*)d_in[0];
    const float* edge_attr= (const float*)d_in[1];
    const float* Wn_in    = (const float*)d_in[2];
    const float* bn_in    = (const float*)d_in[3];
    const float* We_in    = (const float*)d_in[4];
    const float* be_in    = (const float*)d_in[5];
    const float* We_l     = (const float*)d_in[6];
    const float* be_l     = (const float*)d_in[7];
    const float* Wn_l     = (const float*)d_in[8];
    const float* bn_l     = (const float*)d_in[9];
    const float* Wout     = (const float*)d_in[10];
    const float* bout     = (const float*)d_in[11];
    const int*   edge_index = (const int*)d_in[12];
    const int*   batch    = (const int*)d_in[13];
    const int*   cand     = (const int*)d_in[14];
    float* out = (float*)d_out;

    const int TB = 256;
    const int gE  = (EE + TB - 1) / TB;
    const int gE2 = (EE / 2 + TB - 1) / TB;
    const int gN  = (NN + TB - 1) / TB;
    const int gC  = (NC + TB - 1) / TB;

    // counting sort by dst + e init (sorted order)
    k_zero<<<NB, TB>>>(0);
    k_hist<<<gE, TB>>>(edge_index);
    k_scan1<<<NB, TB>>>();
    k_scan2<<<1, 512>>>();
    k_scan3<<<NB, TB>>>();
    k_scatter<<<gE, TB>>>(edge_index, edge_attr, We_in, be_in);
    k_init_nodes<<<gN, TB>>>(x, Wn_in, bn_in, We_l);
    for (int l = 0; l < NL; l++) {
        k_edge<<<gE2, TB>>>(We_l, be_l, l);
        k_node<<<gN, TB>>>(Wn_l, bn_l, We_l, l, (l == NL - 1) ? 1 : 0);
    }
    k_cand<<<gC, TB>>>(cand, batch, Wout, bout);
    k_shift<<<gC, TB>>>(cand, batch, out);
    k_finish<<<gC, TB>>>(cand, batch, out);
}